// round 16
// baseline (speedup 1.0000x reference)
#include <cuda_runtime.h>
#include <cuda_bf16.h>
#include <cstdint>
#include <mma.h>

using namespace nvcuda;
typedef __nv_bfloat16 bf16;
typedef unsigned int u32;

#define CB 4
#define CN 1024
#define CD 512
#define CH 8
#define CDH 64
#define CTC 512

// ---------------- scratch (device globals; allocations forbidden) -----------
__device__ float g_film[CB * 2 * CD];
__device__ bf16  g_xh[CB * CN * CD],  g_xl[CB * CN * CD];
__device__ bf16  g_xnh[CB * CN * CD], g_xnl[CB * CN * CD];
__device__ bf16  g_wqh[CD * CD],      g_wql[CD * CD];
__device__ bf16  g_wkvh[2 * CD * CD], g_wkvl[2 * CD * CD];
__device__ bf16  g_woh[CD * CD],      g_wol[CD * CD];
__device__ bf16  g_qh[CB * CH * CN * CDH], g_ql[CB * CH * CN * CDH];
__device__ bf16  g_kh[CB * CH * CN * CDH], g_kl[CB * CH * CN * CDH];
__device__ bf16  g_vh[CB * CH * CN * CDH], g_vl[CB * CH * CN * CDH];
__device__ bf16  g_oh[CB * CN * CD],  g_ol[CB * CN * CD];
__device__ bf16  g_biasb[CB * CH * CN * CN];            // 64 MB bf16

__device__ __forceinline__ void split2(float v, bf16& h, bf16& l) {
  h = __float2bfloat16(v);
  l = __float2bfloat16(v - __bfloat162float(h));
}
__device__ __forceinline__ u32 pack2(bf16 a, bf16 b) {
  __nv_bfloat162 t = __halves2bfloat162(a, b);
  return *(u32*)&t;
}
__device__ __forceinline__ void pack_hl2(float x, float y, u32& h, u32& l) {
  bf16 hx, lx, hy, ly;
  split2(x, hx, lx);
  split2(y, hy, ly);
  h = pack2(hx, hy);
  l = pack2(lx, ly);
}

// ---------------- PTX helpers -----------------------------------------------
__device__ __forceinline__ void cp16(u32 dst, const void* src) {
  asm volatile("cp.async.cg.shared.global [%0], [%1], 16;" :: "r"(dst), "l"(src));
}
__device__ __forceinline__ void cp_commit() {
  asm volatile("cp.async.commit_group;");
}
__device__ __forceinline__ void cp_wait0() {
  asm volatile("cp.async.wait_group 0;");
}
__device__ __forceinline__ void cp_wait1() {
  asm volatile("cp.async.wait_group 1;");
}
__device__ __forceinline__ void ldm_x4(u32& r0, u32& r1, u32& r2, u32& r3, u32 a) {
  asm volatile("ldmatrix.sync.aligned.m8n8.x4.shared.b16 {%0,%1,%2,%3}, [%4];"
               : "=r"(r0), "=r"(r1), "=r"(r2), "=r"(r3) : "r"(a));
}
__device__ __forceinline__ void ldm_x2(u32& r0, u32& r1, u32 a) {
  asm volatile("ldmatrix.sync.aligned.m8n8.x2.shared.b16 {%0,%1}, [%2];"
               : "=r"(r0), "=r"(r1) : "r"(a));
}
__device__ __forceinline__ void ldm_x2t(u32& r0, u32& r1, u32 a) {
  asm volatile("ldmatrix.sync.aligned.m8n8.x2.trans.shared.b16 {%0,%1}, [%2];"
               : "=r"(r0), "=r"(r1) : "r"(a));
}
__device__ __forceinline__ void mma_bf(float* d, const u32* a, u32 b0, u32 b1) {
  asm volatile(
      "mma.sync.aligned.m16n8k16.row.col.f32.bf16.bf16.f32 "
      "{%0,%1,%2,%3}, {%4,%5,%6,%7}, {%8,%9}, {%0,%1,%2,%3};"
      : "+f"(d[0]), "+f"(d[1]), "+f"(d[2]), "+f"(d[3])
      : "r"(a[0]), "r"(a[1]), "r"(a[2]), "r"(a[3]), "r"(b0), "r"(b1));
}

// ---------------- prep: converts + FiLM in one launch -----------------------
__device__ __forceinline__ void conv_body(const float* __restrict__ src,
                                          bf16* __restrict__ hp,
                                          bf16* __restrict__ lp, int blk) {
  int i = (blk * 256 + threadIdx.x) * 4;
  float4 v = *(const float4*)(src + i);
  bf16 h0, h1, h2, h3, l0, l1, l2, l3;
  split2(v.x, h0, l0);
  split2(v.y, h1, l1);
  split2(v.z, h2, l2);
  split2(v.w, h3, l3);
  ((__nv_bfloat162*)(hp + i))[0] = __halves2bfloat162(h0, h1);
  ((__nv_bfloat162*)(hp + i))[1] = __halves2bfloat162(h2, h3);
  ((__nv_bfloat162*)(lp + i))[0] = __halves2bfloat162(l0, l1);
  ((__nv_bfloat162*)(lp + i))[1] = __halves2bfloat162(l2, l3);
}

__device__ __forceinline__ void film_body(const float* __restrict__ timep,
                                          const float* __restrict__ Wt,
                                          const float* __restrict__ bt, int fb) {
  __shared__ float st[CTC];
  const int b = fb >> 7;
  const int tid = threadIdx.x;
  for (int t = tid; t < CTC; t += 256) {
    float v = timep[b * CTC + t];
    st[t] = v / (1.f + __expf(-v));
  }
  __syncthreads();
  const int wid = tid >> 5;
  const int lane = tid & 31;
  const int o = (fb & 127) * 8 + wid;
  const float* wr = Wt + (size_t)o * CTC;
  float acc = 0.f;
#pragma unroll
  for (int itr = 0; itr < 4; ++itr) {
    int k = itr * 128 + lane * 4;
    float4 wv = *(const float4*)(wr + k);
    acc += wv.x * st[k] + wv.y * st[k + 1] + wv.z * st[k + 2] + wv.w * st[k + 3];
  }
#pragma unroll
  for (int off = 16; off; off >>= 1) acc += __shfl_xor_sync(0xffffffffu, acc, off);
  if (lane == 0) g_film[b * 1024 + o] = acc + bt[o];
}

__global__ void __launch_bounds__(256) prep_kernel(
    const float* __restrict__ x, const float* __restrict__ Wq,
    const float* __restrict__ Wkv, const float* __restrict__ Wo,
    const float* __restrict__ timep, const float* __restrict__ Wt,
    const float* __restrict__ bt) {
  int blk = blockIdx.x;
  if (blk < 2048) conv_body(x, g_xh, g_xl, blk);
  else if (blk < 2304) conv_body(Wq, g_wqh, g_wql, blk - 2048);
  else if (blk < 2816) conv_body(Wkv, g_wkvh, g_wkvl, blk - 2304);
  else if (blk < 3072) conv_body(Wo, g_woh, g_wol, blk - 2816);
  else film_body(timep, Wt, bt, blk - 3072);
}

// ---------------- LayerNorm + FiLM + mask -> hi/lo bf16 ---------------------
__global__ void __launch_bounds__(128) ln_film_kernel(
    const float* __restrict__ x, const float* __restrict__ gamma,
    const float* __restrict__ seq_mask) {
  const int row = blockIdx.x;
  const int b = row >> 10;
  const int tid = threadIdx.x;
  const float* xr = x + (size_t)row * CD;
  float4 xv = *(const float4*)(xr + tid * 4);
  float s = xv.x + xv.y + xv.z + xv.w;
  float sq = xv.x * xv.x + xv.y * xv.y + xv.z * xv.z + xv.w * xv.w;
#pragma unroll
  for (int off = 16; off; off >>= 1) {
    s += __shfl_xor_sync(0xffffffffu, s, off);
    sq += __shfl_xor_sync(0xffffffffu, sq, off);
  }
  __shared__ float rs[4], rq[4];
  const int w = tid >> 5;
  if ((tid & 31) == 0) { rs[w] = s; rq[w] = sq; }
  __syncthreads();
  s = rs[0] + rs[1] + rs[2] + rs[3];
  sq = rq[0] + rq[1] + rq[2] + rq[3];
  const float mu = s * (1.f / 512.f);
  const float var = sq * (1.f / 512.f) - mu * mu;
  const float rstd = rsqrtf(var + 1e-5f);
  float4 g = *(const float4*)(gamma + tid * 4);
  const float* fl = g_film + b * 1024;
  float4 sc = *(const float4*)(fl + tid * 4);
  float4 sh = *(const float4*)(fl + 512 + tid * 4);
  const float msk = seq_mask[row];
  float4 o;
  o.x = (((xv.x - mu) * rstd) * g.x * (sc.x + 1.f) + sh.x) * msk;
  o.y = (((xv.y - mu) * rstd) * g.y * (sc.y + 1.f) + sh.y) * msk;
  o.z = (((xv.z - mu) * rstd) * g.z * (sc.z + 1.f) + sh.z) * msk;
  o.w = (((xv.w - mu) * rstd) * g.w * (sc.w + 1.f) + sh.w) * msk;
  const int idx = row * CD + tid * 4;
  bf16 h0, h1, h2, h3, l0, l1, l2, l3;
  split2(o.x, h0, l0);
  split2(o.y, h1, l1);
  split2(o.z, h2, l2);
  split2(o.w, h3, l3);
  ((__nv_bfloat162*)(g_xnh + idx))[0] = __halves2bfloat162(h0, h1);
  ((__nv_bfloat162*)(g_xnh + idx))[1] = __halves2bfloat162(h2, h3);
  ((__nv_bfloat162*)(g_xnl + idx))[0] = __halves2bfloat162(l0, l1);
  ((__nv_bfloat162*)(g_xnl + idx))[1] = __halves2bfloat162(l2, l3);
}

// ---------------- GEMM body: cp.async double-buffered, wmma hi/lo -----------
#define GLD 40
#define GSTG 40960
#define GEMM_SMEM 81920

__device__ __forceinline__ void gemm_stage(
    u32 sbase, const bf16* __restrict__ Ah, const bf16* __restrict__ Al,
    const bf16* __restrict__ Bh, const bf16* __restrict__ Bl,
    int mBase, int nBase, int kb, int tid) {
#pragma unroll
  for (int it = 0; it < 8; ++it) {
    int e = tid + (it << 8);
    int arr = e >> 9;
    int rem = e & 511;
    int row = rem >> 2;
    int c8 = (rem & 3) << 3;
    const bf16* sp = (arr == 0) ? Ah : (arr == 1) ? Al : (arr == 2) ? Bh : Bl;
    int rb = (arr < 2) ? mBase : nBase;
    u32 dst = sbase + (u32)(arr * 10240 + (row * GLD + c8) * 2);
    cp16(dst, sp + (size_t)(rb + row) * 512 + kb + c8);
  }
}

__device__ __forceinline__ void gemm_body(
    int bx, int by,
    const bf16* __restrict__ Ah, const bf16* __restrict__ Al,
    const bf16* __restrict__ Bh, const bf16* __restrict__ Bl,
    float* __restrict__ Cout, const float* __restrict__ seq_mask, int mode) {
  extern __shared__ char smem_raw[];
  const u32 sb = (u32)__cvta_generic_to_shared(smem_raw);
  const int tid = threadIdx.x;
  const int wid = tid >> 5;
  const int lane = tid & 31;
  const int wM = wid >> 2;
  const int wN = wid & 3;
  const int mBase = by << 7;
  const int nBase = bx << 7;

  wmma::fragment<wmma::accumulator, 16, 16, 16, float> acc[4][2];
#pragma unroll
  for (int mf = 0; mf < 4; ++mf) {
#pragma unroll
    for (int nf = 0; nf < 2; ++nf) wmma::fill_fragment(acc[mf][nf], 0.f);
  }

  gemm_stage(sb, Ah, Al, Bh, Bl, mBase, nBase, 0, tid);
  cp_commit();

  int buf = 0;
  for (int kb = 0; kb < 512; kb += 32) {
    if (kb + 32 < 512) {
      gemm_stage(sb + (u32)((buf ^ 1) * GSTG), Ah, Al, Bh, Bl, mBase, nBase,
                 kb + 32, tid);
      cp_commit();
      cp_wait1();
    } else {
      cp_wait0();
    }
    __syncthreads();

    bf16* base = (bf16*)(smem_raw + buf * GSTG);
    bf16* sAh = base;
    bf16* sAl = base + 5120;
    bf16* sBh = base + 10240;
    bf16* sBl = base + 15360;
#pragma unroll
    for (int ks = 0; ks < 32; ks += 16) {
      wmma::fragment<wmma::matrix_b, 16, 16, 16, bf16, wmma::col_major> fbh[2], fbl[2];
#pragma unroll
      for (int nf = 0; nf < 2; ++nf) {
        wmma::load_matrix_sync(fbh[nf], sBh + (wN * 32 + nf * 16) * GLD + ks, GLD);
        wmma::load_matrix_sync(fbl[nf], sBl + (wN * 32 + nf * 16) * GLD + ks, GLD);
      }
#pragma unroll
      for (int mf = 0; mf < 4; ++mf) {
        wmma::fragment<wmma::matrix_a, 16, 16, 16, bf16, wmma::row_major> fah, fal;
        wmma::load_matrix_sync(fah, sAh + (wM * 64 + mf * 16) * GLD + ks, GLD);
        wmma::load_matrix_sync(fal, sAl + (wM * 64 + mf * 16) * GLD + ks, GLD);
#pragma unroll
        for (int nf = 0; nf < 2; ++nf) {
          wmma::mma_sync(acc[mf][nf], fah, fbh[nf], acc[mf][nf]);
          wmma::mma_sync(acc[mf][nf], fah, fbl[nf], acc[mf][nf]);
          wmma::mma_sync(acc[mf][nf], fal, fbh[nf], acc[mf][nf]);
        }
      }
    }
    __syncthreads();
    buf ^= 1;
  }

  float* sW = (float*)smem_raw + wid * 64 * 36;
#pragma unroll
  for (int mf = 0; mf < 4; ++mf) {
#pragma unroll
    for (int nf = 0; nf < 2; ++nf) {
      wmma::store_matrix_sync(sW + mf * 16 * 36 + nf * 16, acc[mf][nf], 36,
                              wmma::mem_row_major);
    }
  }
  __syncwarp();
  const int cp2 = (lane & 15) * 2;
  const int rsub = lane >> 4;
#pragma unroll 4
  for (int it = 0; it < 32; ++it) {
    int rr = it * 2 + rsub;
    float v0 = sW[rr * 36 + cp2];
    float v1 = sW[rr * 36 + cp2 + 1];
    int m = mBase + wM * 64 + rr;
    int n = nBase + wN * 32 + cp2;
    int b = m >> 10;
    int i = m & 1023;
    if (mode == 2) {
      float msk = seq_mask[m];
      *(float2*)(Cout + (size_t)m * 512 + n) = make_float2(v0 * msk, v1 * msk);
    } else if (mode == 0) {
      int h = n >> 6;
      int d = n & 63;
      size_t idx = (((size_t)(b * 8 + h)) * 1024 + i) * 64 + d;
      u32 ph, pl;
      pack_hl2(v0 * 0.125f, v1 * 0.125f, ph, pl);
      *(u32*)(g_qh + idx) = ph;
      *(u32*)(g_ql + idx) = pl;
    } else {
      int n2 = n & 511;
      int h = n2 >> 6;
      int d = n2 & 63;
      size_t idx = (((size_t)(b * 8 + h)) * 1024 + i) * 64 + d;
      u32 ph, pl;
      pack_hl2(v0, v1, ph, pl);
      if (n < 512) {
        *(u32*)(g_kh + idx) = ph;
        *(u32*)(g_kl + idx) = pl;
      } else {
        *(u32*)(g_vh + idx) = ph;
        *(u32*)(g_vl + idx) = pl;
      }
    }
  }
}

// ---------------- Q + KV projections ----------------------------------------
__global__ void __launch_bounds__(256) qkv_gemm_kernel(
    const float* __restrict__ seq_mask) {
  const int q = blockIdx.x;
  if (q < 128) {
    gemm_body(q & 3, q >> 2, g_xnh, g_xnl, g_wqh, g_wql, nullptr, seq_mask, 0);
  } else {
    int t = q - 128;
    gemm_body(t & 7, t >> 3, g_xh, g_xl, g_wkvh, g_wkvl, nullptr, seq_mask, 1);
  }
}

// ---------------- out projection --------------------------------------------
__global__ void __launch_bounds__(256) out_gemm_kernel(
    float* __restrict__ out, const float* __restrict__ seq_mask) {
  gemm_body(blockIdx.x & 3, blockIdx.x >> 2, g_oh, g_ol, g_woh, g_wol, out,
            seq_mask, 2);
}

// ---------------- bias projection: 2 cols/thread, low regs, grid 8192 -------
__global__ void __launch_bounds__(256) bias_kernel(
    const float* __restrict__ ab, const float* __restrict__ Wb,
    const float* __restrict__ bb, const float* __restrict__ seq_mask) {
  __shared__ float sWb[128];
  __shared__ float sbb[8];
  const int blk = blockIdx.x;          // 8192 = B * N * 2
  const int b = blk >> 11;
  const int rem = blk & 2047;
  const int i = rem >> 1;
  const int half = rem & 1;
  const int tid = threadIdx.x;
  if (tid < 128) sWb[tid] = Wb[tid];
  if (tid < 8) sbb[tid] = bb[tid];
  __syncthreads();
  const int j0 = half * 512 + tid * 2;
  float acc[8][2];
#pragma unroll
  for (int h = 0; h < 8; ++h) {
    float v = sbb[h];
    acc[h][0] = v;
    acc[h][1] = v;
  }
  const float* abp = ab + ((size_t)b * 16 * 1024 + i) * 1024 + j0;
#pragma unroll 4
  for (int a = 0; a < 16; ++a) {
    float2 v = *(const float2*)(abp + (size_t)a * 1024 * 1024);
#pragma unroll
    for (int h = 0; h < 8; ++h) {
      float w = sWb[h * 16 + a];
      acc[h][0] += w * v.x;
      acc[h][1] += w * v.y;
    }
  }
  const float mi = seq_mask[b * 1024 + i];
  float2 mj = *(const float2*)(seq_mask + b * 1024 + j0);
  const float p0 = -(1.f - mi * mj.x) * 1e6f;
  const float p1 = -(1.f - mi * mj.y) * 1e6f;
  bf16* outp = g_biasb + ((size_t)(b * 8) * 1024 + i) * 1024 + j0;
#pragma unroll
  for (int h = 0; h < 8; ++h) {
    __nv_bfloat162 o01 = __floats2bfloat162_rn(acc[h][0] + p0, acc[h][1] + p1);
    *(__nv_bfloat162*)(outp + (size_t)h * 1024 * 1024) = o01;
  }
}

// ---------------- FA2 attention: 3 blocks/SM (Q in regs, 1 bias buffer) -----
// smem (bytes): stage s at s*32768: Kh(8K) Kl(8K) Vh(8K) Vl(8K)
//               bias at 65536: 64 x 72 bf16 (9216)       total 74752
#define KVSTG 32768
#define ABIAS 65536
#define ATTN_SMEM 74752

__device__ __forceinline__ void stage_kv(
    u32 base, const bf16* kh, const bf16* kl, const bf16* vh, const bf16* vl,
    int jt, int tid) {
#pragma unroll
  for (int it = 0; it < 4; ++it) {
    int idx = it * 128 + tid;
    int row = idx >> 3;
    int c = idx & 7;
    u32 off = (u32)(row * 128 + ((c ^ (row & 7)) << 4));
    size_t g = (size_t)jt * 4096 + row * 64 + c * 8;
    cp16(base + off, kh + g);
    cp16(base + 8192u + off, kl + g);
    cp16(base + 16384u + off, vh + g);
    cp16(base + 24576u + off, vl + g);
  }
}

__device__ __forceinline__ void stage_bias(u32 base, const bf16* bg, int jt,
                                           int tid) {
#pragma unroll
  for (int it = 0; it < 4; ++it) {
    int idx = it * 128 + tid;
    int row = idx >> 3;
    int c = idx & 7;
    cp16(base + (u32)(row * 144 + (c << 4)),
         bg + (size_t)row * 1024 + jt * 64 + c * 8);
  }
}

__global__ void __launch_bounds__(128, 3) attn_fa2() {
  extern __shared__ char smem_raw[];
  const u32 sb = (u32)__cvta_generic_to_shared(smem_raw);
  const int bh = blockIdx.y;
  const int itile = blockIdx.x;
  const int tid = threadIdx.x;
  const int wid = tid >> 5;
  const int lane = tid & 31;

  const bf16* qh = g_qh + (size_t)bh * 65536 + itile * 4096;
  const bf16* ql = g_ql + (size_t)bh * 65536 + itile * 4096;
  const bf16* kh = g_kh + (size_t)bh * 65536;
  const bf16* kl = g_kl + (size_t)bh * 65536;
  const bf16* vh = g_vh + (size_t)bh * 65536;
  const bf16* vl = g_vl + (size_t)bh * 65536;
  const bf16* bg = g_biasb + ((size_t)bh * 1024 + itile * 64) * 1024;

  // ---- prologue A: stage Q into stage-0 area (temporarily) ----
#pragma unroll
  for (int it = 0; it < 4; ++it) {
    int idx = it * 128 + tid;
    int row = idx >> 3;
    int c = idx & 7;
    u32 off = (u32)(row * 128 + ((c ^ (row & 7)) << 4));
    cp16(sb + off, qh + row * 64 + c * 8);
    cp16(sb + 8192u + off, ql + row * 64 + c * 8);
  }
  cp_commit();
  cp_wait0();
  __syncthreads();

  // ---- prologue B: Q fragments into registers (reused all 16 tiles) ----
  u32 fqh[4][4], fql[4][4];
#pragma unroll
  for (int ks = 0; ks < 4; ++ks) {
    int row = wid * 16 + (lane & 15);
    int ch = 2 * ks + (lane >> 4);
    u32 off = (u32)(row * 128 + ((ch ^ (row & 7)) << 4));
    ldm_x4(fqh[ks][0], fqh[ks][1], fqh[ks][2], fqh[ks][3], sb + off);
    ldm_x4(fql[ks][0], fql[ks][1], fql[ks][2], fql[ks][3], sb + 8192u + off);
  }
  __syncthreads();   // all warps done reading Q smem; stage-0 reusable

  // ---- prologue C: stage KV tile 0 + bias tile 0 ----
  stage_kv(sb, kh, kl, vh, vl, 0, tid);
  stage_bias(sb + ABIAS, bg, 0, tid);
  cp_commit();

  float o[8][4];
#pragma unroll
  for (int nf = 0; nf < 8; ++nf) {
    o[nf][0] = 0.f; o[nf][1] = 0.f; o[nf][2] = 0.f; o[nf][3] = 0.f;
  }
  float m0 = -1e30f, m1 = -1e30f, l0 = 0.f, l1 = 0.f;
  const int qrow = wid * 16 + (lane >> 2);

  for (int jt = 0; jt < 16; ++jt) {
    const int buf = jt & 1;
    if (jt + 1 < 16) {
      stage_kv(sb + (u32)((1 - buf) * KVSTG), kh, kl, vh, vl, jt + 1, tid);
      cp_commit();
      cp_wait1();   // all but the KV(jt+1) group done => KV(jt), bias(jt) ready
    } else {
      cp_wait0();
    }
    __syncthreads();

    const u32 kbs = sb + (u32)(buf * KVSTG);
    const u32 klbs = kbs + 8192u;
    const u32 vbs = kbs + 16384u;
    const u32 vlbs = kbs + 24576u;
    const bf16* bs = (const bf16*)(smem_raw + ABIAS);

    // ---- S init from the (single) bias buffer ----
    float s[8][4];
#pragma unroll
    for (int nf = 0; nf < 8; ++nf) {
      const bf16* bp = bs + qrow * 72 + nf * 8 + 2 * (lane & 3);
      float2 p0 = __bfloat1622float2(*(const __nv_bfloat162*)bp);
      float2 p1 = __bfloat1622float2(*(const __nv_bfloat162*)(bp + 8 * 72));
      s[nf][0] = p0.x; s[nf][1] = p0.y;
      s[nf][2] = p1.x; s[nf][3] = p1.y;
    }
    __syncthreads();   // bias buffer fully consumed by all warps
    if (jt + 1 < 16) {
      stage_bias(sb + ABIAS, bg, jt + 1, tid);
      cp_commit();     // committed BEFORE next iter's KV commit => covered by wait1
    }

    // ---- S += Qh Kh^T + Qh Kl^T + Ql Kh^T (Q from registers) ----
#pragma unroll
    for (int ks = 0; ks < 4; ++ks) {
#pragma unroll
      for (int nf = 0; nf < 8; ++nf) {
        int row = nf * 8 + (lane & 7);
        int ch = 2 * ks + ((lane >> 3) & 1);
        u32 off = (u32)(row * 128 + ((ch ^ (row & 7)) << 4));
        u32 b0, b1, c0, c1;
        ldm_x2(b0, b1, kbs + off);
        ldm_x2(c0, c1, klbs + off);
        mma_bf(s[nf], fqh[ks], b0, b1);
        mma_bf(s[nf], fqh[ks], c0, c1);
        mma_bf(s[nf], fql[ks], b0, b1);
      }
    }

    // ---- online softmax ----
    float mx0 = fmaxf(s[0][0], s[0][1]);
    float mx1 = fmaxf(s[0][2], s[0][3]);
#pragma unroll
    for (int nf = 1; nf < 8; ++nf) {
      mx0 = fmaxf(mx0, fmaxf(s[nf][0], s[nf][1]));
      mx1 = fmaxf(mx1, fmaxf(s[nf][2], s[nf][3]));
    }
    mx0 = fmaxf(mx0, __shfl_xor_sync(0xffffffffu, mx0, 1));
    mx0 = fmaxf(mx0, __shfl_xor_sync(0xffffffffu, mx0, 2));
    mx1 = fmaxf(mx1, __shfl_xor_sync(0xffffffffu, mx1, 1));
    mx1 = fmaxf(mx1, __shfl_xor_sync(0xffffffffu, mx1, 2));
    const float mn0 = fmaxf(m0, mx0);
    const float mn1 = fmaxf(m1, mx1);
    const float a0 = __expf(m0 - mn0);
    const float a1 = __expf(m1 - mn1);
    m0 = mn0;
    m1 = mn1;
    float sum0 = 0.f, sum1 = 0.f;
#pragma unroll
    for (int nf = 0; nf < 8; ++nf) {
      s[nf][0] = __expf(s[nf][0] - mn0);
      s[nf][1] = __expf(s[nf][1] - mn0);
      s[nf][2] = __expf(s[nf][2] - mn1);
      s[nf][3] = __expf(s[nf][3] - mn1);
      sum0 += s[nf][0] + s[nf][1];
      sum1 += s[nf][2] + s[nf][3];
    }
    sum0 += __shfl_xor_sync(0xffffffffu, sum0, 1);
    sum0 += __shfl_xor_sync(0xffffffffu, sum0, 2);
    sum1 += __shfl_xor_sync(0xffffffffu, sum1, 1);
    sum1 += __shfl_xor_sync(0xffffffffu, sum1, 2);
    l0 = l0 * a0 + sum0;
    l1 = l1 * a1 + sum1;
#pragma unroll
    for (int nf = 0; nf < 8; ++nf) {
      o[nf][0] *= a0;
      o[nf][1] *= a0;
      o[nf][2] *= a1;
      o[nf][3] *= a1;
    }

    // ---- O += Ph Vh + Ph Vl + Pl Vh ----
#pragma unroll
    for (int kf = 0; kf < 4; ++kf) {
      u32 ph[4], pl[4];
      pack_hl2(s[2 * kf][0], s[2 * kf][1], ph[0], pl[0]);
      pack_hl2(s[2 * kf][2], s[2 * kf][3], ph[1], pl[1]);
      pack_hl2(s[2 * kf + 1][0], s[2 * kf + 1][1], ph[2], pl[2]);
      pack_hl2(s[2 * kf + 1][2], s[2 * kf + 1][3], ph[3], pl[3]);
      int row = kf * 16 + (lane & 15);
#pragma unroll
      for (int nf = 0; nf < 8; ++nf) {
        u32 off = (u32)(row * 128 + ((nf ^ (row & 7)) << 4));
        u32 b0, b1, c0, c1;
        ldm_x2t(b0, b1, vbs + off);
        ldm_x2t(c0, c1, vlbs + off);
        mma_bf(o[nf], ph, b0, b1);
        mma_bf(o[nf], ph, c0, c1);
        mma_bf(o[nf], pl, b0, b1);
      }
    }
    __syncthreads();   // stage buffer may be overwritten at next loop top
  }

  // ---- epilogue ----
  const int b = bh >> 3;
  const int h = bh & 7;
  const float inv0 = 1.f / l0;
  const float inv1 = 1.f / l1;
  const int row0 = itile * 64 + qrow;
#pragma unroll
  for (int nf = 0; nf < 8; ++nf) {
    const int d0 = nf * 8 + 2 * (lane & 3);
    size_t idx = ((size_t)(b * 1024 + row0)) * 512 + h * 64 + d0;
    u32 hh, ll;
    pack_hl2(o[nf][0] * inv0, o[nf][1] * inv0, hh, ll);
    *(u32*)(g_oh + idx) = hh;
    *(u32*)(g_ol + idx) = ll;
    size_t idx1 = idx + 8 * 512;
    pack_hl2(o[nf][2] * inv1, o[nf][3] * inv1, hh, ll);
    *(u32*)(g_oh + idx1) = hh;
    *(u32*)(g_ol + idx1) = ll;
  }
}

// ---------------- launch ----------------------------------------------------
extern "C" void kernel_launch(void* const* d_in, const int* in_sizes, int n_in,
                              void* d_out, int out_size) {
  const float* x        = (const float*)d_in[0];
  const float* timep    = (const float*)d_in[1];
  const float* ab       = (const float*)d_in[2];
  const float* seq_mask = (const float*)d_in[3];
  const float* gamma    = (const float*)d_in[4];
  const float* Wt       = (const float*)d_in[5];
  const float* bt       = (const float*)d_in[6];
  const float* Wq       = (const float*)d_in[7];
  const float* Wkv      = (const float*)d_in[8];
  const float* Wo       = (const float*)d_in[9];
  const float* Wb       = (const float*)d_in[10];
  const float* bb       = (const float*)d_in[11];
  float* out = (float*)d_out;

  cudaFuncSetAttribute(qkv_gemm_kernel,
                       cudaFuncAttributeMaxDynamicSharedMemorySize, GEMM_SMEM);
  cudaFuncSetAttribute(out_gemm_kernel,
                       cudaFuncAttributeMaxDynamicSharedMemorySize, GEMM_SMEM);
  cudaFuncSetAttribute(attn_fa2, cudaFuncAttributeMaxDynamicSharedMemorySize,
                       ATTN_SMEM);

  // converts + FiLM (independent of everything)
  prep_kernel<<<3584, 256>>>(x, Wq, Wkv, Wo, timep, Wt, bt);
  // LayerNorm + FiLM (needs film)
  ln_film_kernel<<<CB * CN, 128>>>(x, gamma, seq_mask);
  // Q + KV projections
  qkv_gemm_kernel<<<384, 256, GEMM_SMEM>>>(seq_mask);
  // bias projection (memory-bound; low-reg, high-occupancy variant)
  bias_kernel<<<CB * CN * 2, 256>>>(ab, Wb, bb, seq_mask);
  // fused attention (3 blocks/SM: Q in registers, single bias buffer)
  attn_fa2<<<dim3(16, 32), 128, ATTN_SMEM>>>();
  // out = O @ Wo^T, * mask
  out_gemm_kernel<<<128, 256, GEMM_SMEM>>>(out, seq_mask);
}

// round 17
// speedup vs baseline: 1.0200x; 1.0200x over previous
#include <cuda_runtime.h>
#include <cuda_bf16.h>
#include <cstdint>
#include <mma.h>

using namespace nvcuda;
typedef __nv_bfloat16 bf16;
typedef unsigned int u32;

#define CB 4
#define CN 1024
#define CD 512
#define CH 8
#define CDH 64
#define CTC 512

// ---------------- scratch (device globals; allocations forbidden) -----------
__device__ float g_film[CB * 2 * CD];
__device__ bf16  g_xh[CB * CN * CD],  g_xl[CB * CN * CD];
__device__ bf16  g_xnh[CB * CN * CD], g_xnl[CB * CN * CD];
__device__ bf16  g_wqh[CD * CD],      g_wql[CD * CD];
__device__ bf16  g_wkvh[2 * CD * CD], g_wkvl[2 * CD * CD];
__device__ bf16  g_woh[CD * CD],      g_wol[CD * CD];
__device__ bf16  g_qh[CB * CH * CN * CDH], g_ql[CB * CH * CN * CDH];
__device__ bf16  g_kh[CB * CH * CN * CDH], g_kl[CB * CH * CN * CDH];
__device__ bf16  g_vh[CB * CH * CN * CDH], g_vl[CB * CH * CN * CDH];
__device__ bf16  g_oh[CB * CN * CD],  g_ol[CB * CN * CD];
__device__ bf16  g_biasb[CB * CH * CN * CN];            // 64 MB bf16

__device__ __forceinline__ void split2(float v, bf16& h, bf16& l) {
  h = __float2bfloat16(v);
  l = __float2bfloat16(v - __bfloat162float(h));
}
__device__ __forceinline__ u32 pack2(bf16 a, bf16 b) {
  __nv_bfloat162 t = __halves2bfloat162(a, b);
  return *(u32*)&t;
}
__device__ __forceinline__ void pack_hl2(float x, float y, u32& h, u32& l) {
  bf16 hx, lx, hy, ly;
  split2(x, hx, lx);
  split2(y, hy, ly);
  h = pack2(hx, hy);
  l = pack2(lx, ly);
}

// ---------------- PTX helpers -----------------------------------------------
__device__ __forceinline__ void cp16(u32 dst, const void* src) {
  asm volatile("cp.async.cg.shared.global [%0], [%1], 16;" :: "r"(dst), "l"(src));
}
__device__ __forceinline__ void cp_commit() {
  asm volatile("cp.async.commit_group;");
}
__device__ __forceinline__ void cp_wait0() {
  asm volatile("cp.async.wait_group 0;");
}
__device__ __forceinline__ void cp_wait1() {
  asm volatile("cp.async.wait_group 1;");
}
__device__ __forceinline__ void ldm_x4(u32& r0, u32& r1, u32& r2, u32& r3, u32 a) {
  asm volatile("ldmatrix.sync.aligned.m8n8.x4.shared.b16 {%0,%1,%2,%3}, [%4];"
               : "=r"(r0), "=r"(r1), "=r"(r2), "=r"(r3) : "r"(a));
}
__device__ __forceinline__ void ldm_x2(u32& r0, u32& r1, u32 a) {
  asm volatile("ldmatrix.sync.aligned.m8n8.x2.shared.b16 {%0,%1}, [%2];"
               : "=r"(r0), "=r"(r1) : "r"(a));
}
__device__ __forceinline__ void ldm_x2t(u32& r0, u32& r1, u32 a) {
  asm volatile("ldmatrix.sync.aligned.m8n8.x2.trans.shared.b16 {%0,%1}, [%2];"
               : "=r"(r0), "=r"(r1) : "r"(a));
}
__device__ __forceinline__ void mma_bf(float* d, const u32* a, u32 b0, u32 b1) {
  asm volatile(
      "mma.sync.aligned.m16n8k16.row.col.f32.bf16.bf16.f32 "
      "{%0,%1,%2,%3}, {%4,%5,%6,%7}, {%8,%9}, {%0,%1,%2,%3};"
      : "+f"(d[0]), "+f"(d[1]), "+f"(d[2]), "+f"(d[3])
      : "r"(a[0]), "r"(a[1]), "r"(a[2]), "r"(a[3]), "r"(b0), "r"(b1));
}

// ---------------- prep: converts + FiLM in one launch -----------------------
__device__ __forceinline__ void conv_body(const float* __restrict__ src,
                                          bf16* __restrict__ hp,
                                          bf16* __restrict__ lp, int blk) {
  int i = (blk * 256 + threadIdx.x) * 4;
  float4 v = *(const float4*)(src + i);
  bf16 h0, h1, h2, h3, l0, l1, l2, l3;
  split2(v.x, h0, l0);
  split2(v.y, h1, l1);
  split2(v.z, h2, l2);
  split2(v.w, h3, l3);
  ((__nv_bfloat162*)(hp + i))[0] = __halves2bfloat162(h0, h1);
  ((__nv_bfloat162*)(hp + i))[1] = __halves2bfloat162(h2, h3);
  ((__nv_bfloat162*)(lp + i))[0] = __halves2bfloat162(l0, l1);
  ((__nv_bfloat162*)(lp + i))[1] = __halves2bfloat162(l2, l3);
}

__device__ __forceinline__ void film_body(const float* __restrict__ timep,
                                          const float* __restrict__ Wt,
                                          const float* __restrict__ bt, int fb) {
  __shared__ float st[CTC];
  const int b = fb >> 7;
  const int tid = threadIdx.x;
  for (int t = tid; t < CTC; t += 256) {
    float v = timep[b * CTC + t];
    st[t] = v / (1.f + __expf(-v));
  }
  __syncthreads();
  const int wid = tid >> 5;
  const int lane = tid & 31;
  const int o = (fb & 127) * 8 + wid;
  const float* wr = Wt + (size_t)o * CTC;
  float acc = 0.f;
#pragma unroll
  for (int itr = 0; itr < 4; ++itr) {
    int k = itr * 128 + lane * 4;
    float4 wv = *(const float4*)(wr + k);
    acc += wv.x * st[k] + wv.y * st[k + 1] + wv.z * st[k + 2] + wv.w * st[k + 3];
  }
#pragma unroll
  for (int off = 16; off; off >>= 1) acc += __shfl_xor_sync(0xffffffffu, acc, off);
  if (lane == 0) g_film[b * 1024 + o] = acc + bt[o];
}

__global__ void __launch_bounds__(256) prep_kernel(
    const float* __restrict__ x, const float* __restrict__ Wq,
    const float* __restrict__ Wkv, const float* __restrict__ Wo,
    const float* __restrict__ timep, const float* __restrict__ Wt,
    const float* __restrict__ bt) {
  int blk = blockIdx.x;
  if (blk < 2048) conv_body(x, g_xh, g_xl, blk);
  else if (blk < 2304) conv_body(Wq, g_wqh, g_wql, blk - 2048);
  else if (blk < 2816) conv_body(Wkv, g_wkvh, g_wkvl, blk - 2304);
  else if (blk < 3072) conv_body(Wo, g_woh, g_wol, blk - 2816);
  else film_body(timep, Wt, bt, blk - 3072);
}

// ---------------- LayerNorm + FiLM + mask -> hi/lo bf16 ---------------------
__global__ void __launch_bounds__(128) ln_film_kernel(
    const float* __restrict__ x, const float* __restrict__ gamma,
    const float* __restrict__ seq_mask) {
  const int row = blockIdx.x;
  const int b = row >> 10;
  const int tid = threadIdx.x;
  const float* xr = x + (size_t)row * CD;
  float4 xv = *(const float4*)(xr + tid * 4);
  float s = xv.x + xv.y + xv.z + xv.w;
  float sq = xv.x * xv.x + xv.y * xv.y + xv.z * xv.z + xv.w * xv.w;
#pragma unroll
  for (int off = 16; off; off >>= 1) {
    s += __shfl_xor_sync(0xffffffffu, s, off);
    sq += __shfl_xor_sync(0xffffffffu, sq, off);
  }
  __shared__ float rs[4], rq[4];
  const int w = tid >> 5;
  if ((tid & 31) == 0) { rs[w] = s; rq[w] = sq; }
  __syncthreads();
  s = rs[0] + rs[1] + rs[2] + rs[3];
  sq = rq[0] + rq[1] + rq[2] + rq[3];
  const float mu = s * (1.f / 512.f);
  const float var = sq * (1.f / 512.f) - mu * mu;
  const float rstd = rsqrtf(var + 1e-5f);
  float4 g = *(const float4*)(gamma + tid * 4);
  const float* fl = g_film + b * 1024;
  float4 sc = *(const float4*)(fl + tid * 4);
  float4 sh = *(const float4*)(fl + 512 + tid * 4);
  const float msk = seq_mask[row];
  float4 o;
  o.x = (((xv.x - mu) * rstd) * g.x * (sc.x + 1.f) + sh.x) * msk;
  o.y = (((xv.y - mu) * rstd) * g.y * (sc.y + 1.f) + sh.y) * msk;
  o.z = (((xv.z - mu) * rstd) * g.z * (sc.z + 1.f) + sh.z) * msk;
  o.w = (((xv.w - mu) * rstd) * g.w * (sc.w + 1.f) + sh.w) * msk;
  const int idx = row * CD + tid * 4;
  bf16 h0, h1, h2, h3, l0, l1, l2, l3;
  split2(o.x, h0, l0);
  split2(o.y, h1, l1);
  split2(o.z, h2, l2);
  split2(o.w, h3, l3);
  ((__nv_bfloat162*)(g_xnh + idx))[0] = __halves2bfloat162(h0, h1);
  ((__nv_bfloat162*)(g_xnh + idx))[1] = __halves2bfloat162(h2, h3);
  ((__nv_bfloat162*)(g_xnl + idx))[0] = __halves2bfloat162(l0, l1);
  ((__nv_bfloat162*)(g_xnl + idx))[1] = __halves2bfloat162(l2, l3);
}

// ---------------- GEMM body: cp.async double-buffered, wmma hi/lo -----------
#define GLD 40
#define GSTG 40960
#define GEMM_SMEM 81920

__device__ __forceinline__ void gemm_stage(
    u32 sbase, const bf16* __restrict__ Ah, const bf16* __restrict__ Al,
    const bf16* __restrict__ Bh, const bf16* __restrict__ Bl,
    int mBase, int nBase, int kb, int tid) {
#pragma unroll
  for (int it = 0; it < 8; ++it) {
    int e = tid + (it << 8);
    int arr = e >> 9;
    int rem = e & 511;
    int row = rem >> 2;
    int c8 = (rem & 3) << 3;
    const bf16* sp = (arr == 0) ? Ah : (arr == 1) ? Al : (arr == 2) ? Bh : Bl;
    int rb = (arr < 2) ? mBase : nBase;
    u32 dst = sbase + (u32)(arr * 10240 + (row * GLD + c8) * 2);
    cp16(dst, sp + (size_t)(rb + row) * 512 + kb + c8);
  }
}

__device__ __forceinline__ void gemm_body(
    int bx, int by,
    const bf16* __restrict__ Ah, const bf16* __restrict__ Al,
    const bf16* __restrict__ Bh, const bf16* __restrict__ Bl,
    float* __restrict__ Cout, const float* __restrict__ seq_mask, int mode) {
  extern __shared__ char smem_raw[];
  const u32 sb = (u32)__cvta_generic_to_shared(smem_raw);
  const int tid = threadIdx.x;
  const int wid = tid >> 5;
  const int lane = tid & 31;
  const int wM = wid >> 2;
  const int wN = wid & 3;
  const int mBase = by << 7;
  const int nBase = bx << 7;

  wmma::fragment<wmma::accumulator, 16, 16, 16, float> acc[4][2];
#pragma unroll
  for (int mf = 0; mf < 4; ++mf) {
#pragma unroll
    for (int nf = 0; nf < 2; ++nf) wmma::fill_fragment(acc[mf][nf], 0.f);
  }

  gemm_stage(sb, Ah, Al, Bh, Bl, mBase, nBase, 0, tid);
  cp_commit();

  int buf = 0;
  for (int kb = 0; kb < 512; kb += 32) {
    if (kb + 32 < 512) {
      gemm_stage(sb + (u32)((buf ^ 1) * GSTG), Ah, Al, Bh, Bl, mBase, nBase,
                 kb + 32, tid);
      cp_commit();
      cp_wait1();
    } else {
      cp_wait0();
    }
    __syncthreads();

    bf16* base = (bf16*)(smem_raw + buf * GSTG);
    bf16* sAh = base;
    bf16* sAl = base + 5120;
    bf16* sBh = base + 10240;
    bf16* sBl = base + 15360;
#pragma unroll
    for (int ks = 0; ks < 32; ks += 16) {
      wmma::fragment<wmma::matrix_b, 16, 16, 16, bf16, wmma::col_major> fbh[2], fbl[2];
#pragma unroll
      for (int nf = 0; nf < 2; ++nf) {
        wmma::load_matrix_sync(fbh[nf], sBh + (wN * 32 + nf * 16) * GLD + ks, GLD);
        wmma::load_matrix_sync(fbl[nf], sBl + (wN * 32 + nf * 16) * GLD + ks, GLD);
      }
#pragma unroll
      for (int mf = 0; mf < 4; ++mf) {
        wmma::fragment<wmma::matrix_a, 16, 16, 16, bf16, wmma::row_major> fah, fal;
        wmma::load_matrix_sync(fah, sAh + (wM * 64 + mf * 16) * GLD + ks, GLD);
        wmma::load_matrix_sync(fal, sAl + (wM * 64 + mf * 16) * GLD + ks, GLD);
#pragma unroll
        for (int nf = 0; nf < 2; ++nf) {
          wmma::mma_sync(acc[mf][nf], fah, fbh[nf], acc[mf][nf]);
          wmma::mma_sync(acc[mf][nf], fah, fbl[nf], acc[mf][nf]);
          wmma::mma_sync(acc[mf][nf], fal, fbh[nf], acc[mf][nf]);
        }
      }
    }
    __syncthreads();
    buf ^= 1;
  }

  float* sW = (float*)smem_raw + wid * 64 * 36;
#pragma unroll
  for (int mf = 0; mf < 4; ++mf) {
#pragma unroll
    for (int nf = 0; nf < 2; ++nf) {
      wmma::store_matrix_sync(sW + mf * 16 * 36 + nf * 16, acc[mf][nf], 36,
                              wmma::mem_row_major);
    }
  }
  __syncwarp();
  const int cp2 = (lane & 15) * 2;
  const int rsub = lane >> 4;
#pragma unroll 4
  for (int it = 0; it < 32; ++it) {
    int rr = it * 2 + rsub;
    float v0 = sW[rr * 36 + cp2];
    float v1 = sW[rr * 36 + cp2 + 1];
    int m = mBase + wM * 64 + rr;
    int n = nBase + wN * 32 + cp2;
    int b = m >> 10;
    int i = m & 1023;
    if (mode == 2) {
      float msk = seq_mask[m];
      *(float2*)(Cout + (size_t)m * 512 + n) = make_float2(v0 * msk, v1 * msk);
    } else if (mode == 0) {
      int h = n >> 6;
      int d = n & 63;
      size_t idx = (((size_t)(b * 8 + h)) * 1024 + i) * 64 + d;
      u32 ph, pl;
      pack_hl2(v0 * 0.125f, v1 * 0.125f, ph, pl);
      *(u32*)(g_qh + idx) = ph;
      *(u32*)(g_ql + idx) = pl;
    } else {
      int n2 = n & 511;
      int h = n2 >> 6;
      int d = n2 & 63;
      size_t idx = (((size_t)(b * 8 + h)) * 1024 + i) * 64 + d;
      u32 ph, pl;
      pack_hl2(v0, v1, ph, pl);
      if (n < 512) {
        *(u32*)(g_kh + idx) = ph;
        *(u32*)(g_kl + idx) = pl;
      } else {
        *(u32*)(g_vh + idx) = ph;
        *(u32*)(g_vl + idx) = pl;
      }
    }
  }
}

// ---------------- Q + KV projections ----------------------------------------
__global__ void __launch_bounds__(256) qkv_gemm_kernel(
    const float* __restrict__ seq_mask) {
  const int q = blockIdx.x;
  if (q < 128) {
    gemm_body(q & 3, q >> 2, g_xnh, g_xnl, g_wqh, g_wql, nullptr, seq_mask, 0);
  } else {
    int t = q - 128;
    gemm_body(t & 7, t >> 3, g_xh, g_xl, g_wkvh, g_wkvl, nullptr, seq_mask, 1);
  }
}

// ---------------- out projection --------------------------------------------
__global__ void __launch_bounds__(256) out_gemm_kernel(
    float* __restrict__ out, const float* __restrict__ seq_mask) {
  gemm_body(blockIdx.x & 3, blockIdx.x >> 2, g_oh, g_ol, g_woh, g_wol, out,
            seq_mask, 2);
}

// ---------------- bias projection: 2 cols/thread, low regs, grid 8192 -------
__global__ void __launch_bounds__(256) bias_kernel(
    const float* __restrict__ ab, const float* __restrict__ Wb,
    const float* __restrict__ bb, const float* __restrict__ seq_mask) {
  __shared__ float sWb[128];
  __shared__ float sbb[8];
  const int blk = blockIdx.x;          // 8192 = B * N * 2
  const int b = blk >> 11;
  const int rem = blk & 2047;
  const int i = rem >> 1;
  const int half = rem & 1;
  const int tid = threadIdx.x;
  if (tid < 128) sWb[tid] = Wb[tid];
  if (tid < 8) sbb[tid] = bb[tid];
  __syncthreads();
  const int j0 = half * 512 + tid * 2;
  float acc[8][2];
#pragma unroll
  for (int h = 0; h < 8; ++h) {
    float v = sbb[h];
    acc[h][0] = v;
    acc[h][1] = v;
  }
  const float* abp = ab + ((size_t)b * 16 * 1024 + i) * 1024 + j0;
#pragma unroll 4
  for (int a = 0; a < 16; ++a) {
    float2 v = *(const float2*)(abp + (size_t)a * 1024 * 1024);
#pragma unroll
    for (int h = 0; h < 8; ++h) {
      float w = sWb[h * 16 + a];
      acc[h][0] += w * v.x;
      acc[h][1] += w * v.y;
    }
  }
  const float mi = seq_mask[b * 1024 + i];
  float2 mj = *(const float2*)(seq_mask + b * 1024 + j0);
  const float p0 = -(1.f - mi * mj.x) * 1e6f;
  const float p1 = -(1.f - mi * mj.y) * 1e6f;
  bf16* outp = g_biasb + ((size_t)(b * 8) * 1024 + i) * 1024 + j0;
#pragma unroll
  for (int h = 0; h < 8; ++h) {
    __nv_bfloat162 o01 = __floats2bfloat162_rn(acc[h][0] + p0, acc[h][1] + p1);
    *(__nv_bfloat162*)(outp + (size_t)h * 1024 * 1024) = o01;
  }
}

// ---------------- FA2 attention (proven R14 config) --------------------------
// smem: [0,8192) Qh | [8192,16384) Ql | stage s at 16384 + s*ASTG:
//   Kh(8192) Kl(8192) Vh(8192) Vl(8192) bias 64x72 bf16 (9216)
#define ASTG 41984
#define ATTN_SMEM (16384 + 2 * ASTG)   // 100352

__device__ __forceinline__ void stage_tile(
    u32 base, const bf16* kh, const bf16* kl, const bf16* vh, const bf16* vl,
    const bf16* bg, int jt, int tid) {
#pragma unroll
  for (int it = 0; it < 4; ++it) {
    int idx = it * 128 + tid;
    int row = idx >> 3;
    int c = idx & 7;
    u32 off = (u32)(row * 128 + ((c ^ (row & 7)) << 4));
    size_t g = (size_t)jt * 4096 + row * 64 + c * 8;
    cp16(base + off, kh + g);
    cp16(base + 8192u + off, kl + g);
    cp16(base + 16384u + off, vh + g);
    cp16(base + 24576u + off, vl + g);
    cp16(base + 32768u + (u32)(row * 144 + (c << 4)),
         bg + (size_t)row * 1024 + jt * 64 + c * 8);
  }
}

__global__ void __launch_bounds__(128) attn_fa2() {
  extern __shared__ char smem_raw[];
  const u32 sb = (u32)__cvta_generic_to_shared(smem_raw);
  const int bh = blockIdx.y;
  const int itile = blockIdx.x;
  const int tid = threadIdx.x;
  const int wid = tid >> 5;
  const int lane = tid & 31;

  const bf16* qh = g_qh + (size_t)bh * 65536 + itile * 4096;
  const bf16* ql = g_ql + (size_t)bh * 65536 + itile * 4096;
  const bf16* kh = g_kh + (size_t)bh * 65536;
  const bf16* kl = g_kl + (size_t)bh * 65536;
  const bf16* vh = g_vh + (size_t)bh * 65536;
  const bf16* vl = g_vl + (size_t)bh * 65536;
  const bf16* bg = g_biasb + ((size_t)bh * 1024 + itile * 64) * 1024;

  // prologue: Q hi/lo + tile 0 in one group
#pragma unroll
  for (int it = 0; it < 4; ++it) {
    int idx = it * 128 + tid;
    int row = idx >> 3;
    int c = idx & 7;
    u32 off = (u32)(row * 128 + ((c ^ (row & 7)) << 4));
    cp16(sb + off, qh + row * 64 + c * 8);
    cp16(sb + 8192u + off, ql + row * 64 + c * 8);
  }
  stage_tile(sb + 16384u, kh, kl, vh, vl, bg, 0, tid);
  cp_commit();

  float o[8][4];
#pragma unroll
  for (int nf = 0; nf < 8; ++nf) {
    o[nf][0] = 0.f; o[nf][1] = 0.f; o[nf][2] = 0.f; o[nf][3] = 0.f;
  }
  float m0 = -1e30f, m1 = -1e30f, l0 = 0.f, l1 = 0.f;
  const int qrow = wid * 16 + (lane >> 2);

  for (int jt = 0; jt < 16; ++jt) {
    const int buf = jt & 1;
    if (jt + 1 < 16) {
      stage_tile(sb + 16384u + (u32)((1 - buf) * ASTG), kh, kl, vh, vl, bg,
                 jt + 1, tid);
      cp_commit();
      cp_wait1();
    } else {
      cp_wait0();
    }
    __syncthreads();

    const u32 kbs = sb + 16384u + (u32)(buf * ASTG);
    const u32 klbs = kbs + 8192u;
    const u32 vbs = kbs + 16384u;
    const u32 vlbs = kbs + 24576u;
    const bf16* bs = (const bf16*)(smem_raw + 16384 + buf * ASTG + 32768);

    // ---- S = bias + Qh Kh^T + Qh Kl^T + Ql Kh^T ----
    float s[8][4];
#pragma unroll
    for (int nf = 0; nf < 8; ++nf) {
      const bf16* bp = bs + qrow * 72 + nf * 8 + 2 * (lane & 3);
      float2 p0 = __bfloat1622float2(*(const __nv_bfloat162*)bp);
      float2 p1 = __bfloat1622float2(*(const __nv_bfloat162*)(bp + 8 * 72));
      s[nf][0] = p0.x; s[nf][1] = p0.y;
      s[nf][2] = p1.x; s[nf][3] = p1.y;
    }
#pragma unroll
    for (int ks = 0; ks < 4; ++ks) {
      u32 fah[4], fal[4];
      {
        int row = wid * 16 + (lane & 15);
        int ch = 2 * ks + (lane >> 4);
        u32 off = (u32)(row * 128 + ((ch ^ (row & 7)) << 4));
        ldm_x4(fah[0], fah[1], fah[2], fah[3], sb + off);
        ldm_x4(fal[0], fal[1], fal[2], fal[3], sb + 8192u + off);
      }
#pragma unroll
      for (int nf = 0; nf < 8; ++nf) {
        int row = nf * 8 + (lane & 7);
        int ch = 2 * ks + ((lane >> 3) & 1);
        u32 off = (u32)(row * 128 + ((ch ^ (row & 7)) << 4));
        u32 b0, b1, c0, c1;
        ldm_x2(b0, b1, kbs + off);
        ldm_x2(c0, c1, klbs + off);
        mma_bf(s[nf], fah, b0, b1);
        mma_bf(s[nf], fah, c0, c1);
        mma_bf(s[nf], fal, b0, b1);
      }
    }

    // ---- online softmax ----
    float mx0 = fmaxf(s[0][0], s[0][1]);
    float mx1 = fmaxf(s[0][2], s[0][3]);
#pragma unroll
    for (int nf = 1; nf < 8; ++nf) {
      mx0 = fmaxf(mx0, fmaxf(s[nf][0], s[nf][1]));
      mx1 = fmaxf(mx1, fmaxf(s[nf][2], s[nf][3]));
    }
    mx0 = fmaxf(mx0, __shfl_xor_sync(0xffffffffu, mx0, 1));
    mx0 = fmaxf(mx0, __shfl_xor_sync(0xffffffffu, mx0, 2));
    mx1 = fmaxf(mx1, __shfl_xor_sync(0xffffffffu, mx1, 1));
    mx1 = fmaxf(mx1, __shfl_xor_sync(0xffffffffu, mx1, 2));
    const float mn0 = fmaxf(m0, mx0);
    const float mn1 = fmaxf(m1, mx1);
    const float a0 = __expf(m0 - mn0);
    const float a1 = __expf(m1 - mn1);
    m0 = mn0;
    m1 = mn1;
    float sum0 = 0.f, sum1 = 0.f;
#pragma unroll
    for (int nf = 0; nf < 8; ++nf) {
      s[nf][0] = __expf(s[nf][0] - mn0);
      s[nf][1] = __expf(s[nf][1] - mn0);
      s[nf][2] = __expf(s[nf][2] - mn1);
      s[nf][3] = __expf(s[nf][3] - mn1);
      sum0 += s[nf][0] + s[nf][1];
      sum1 += s[nf][2] + s[nf][3];
    }
    sum0 += __shfl_xor_sync(0xffffffffu, sum0, 1);
    sum0 += __shfl_xor_sync(0xffffffffu, sum0, 2);
    sum1 += __shfl_xor_sync(0xffffffffu, sum1, 1);
    sum1 += __shfl_xor_sync(0xffffffffu, sum1, 2);
    l0 = l0 * a0 + sum0;
    l1 = l1 * a1 + sum1;
#pragma unroll
    for (int nf = 0; nf < 8; ++nf) {
      o[nf][0] *= a0;
      o[nf][1] *= a0;
      o[nf][2] *= a1;
      o[nf][3] *= a1;
    }

    // ---- O += Ph Vh + Ph Vl + Pl Vh ----
#pragma unroll
    for (int kf = 0; kf < 4; ++kf) {
      u32 ph[4], pl[4];
      pack_hl2(s[2 * kf][0], s[2 * kf][1], ph[0], pl[0]);
      pack_hl2(s[2 * kf][2], s[2 * kf][3], ph[1], pl[1]);
      pack_hl2(s[2 * kf + 1][0], s[2 * kf + 1][1], ph[2], pl[2]);
      pack_hl2(s[2 * kf + 1][2], s[2 * kf + 1][3], ph[3], pl[3]);
      int row = kf * 16 + (lane & 15);
#pragma unroll
      for (int nf = 0; nf < 8; ++nf) {
        u32 off = (u32)(row * 128 + ((nf ^ (row & 7)) << 4));
        u32 b0, b1, c0, c1;
        ldm_x2t(b0, b1, vbs + off);
        ldm_x2t(c0, c1, vlbs + off);
        mma_bf(o[nf], ph, b0, b1);
        mma_bf(o[nf], ph, c0, c1);
        mma_bf(o[nf], pl, b0, b1);
      }
    }
    __syncthreads();
  }

  // ---- epilogue ----
  const int b = bh >> 3;
  const int h = bh & 7;
  const float inv0 = 1.f / l0;
  const float inv1 = 1.f / l1;
  const int row0 = itile * 64 + qrow;
#pragma unroll
  for (int nf = 0; nf < 8; ++nf) {
    const int d0 = nf * 8 + 2 * (lane & 3);
    size_t idx = ((size_t)(b * 1024 + row0)) * 512 + h * 64 + d0;
    u32 hh, ll;
    pack_hl2(o[nf][0] * inv0, o[nf][1] * inv0, hh, ll);
    *(u32*)(g_oh + idx) = hh;
    *(u32*)(g_ol + idx) = ll;
    size_t idx1 = idx + 8 * 512;
    pack_hl2(o[nf][2] * inv1, o[nf][3] * inv1, hh, ll);
    *(u32*)(g_oh + idx1) = hh;
    *(u32*)(g_ol + idx1) = ll;
  }
}

// ---------------- launch: fork bias onto a second stream ---------------------
extern "C" void kernel_launch(void* const* d_in, const int* in_sizes, int n_in,
                              void* d_out, int out_size) {
  const float* x        = (const float*)d_in[0];
  const float* timep    = (const float*)d_in[1];
  const float* ab       = (const float*)d_in[2];
  const float* seq_mask = (const float*)d_in[3];
  const float* gamma    = (const float*)d_in[4];
  const float* Wt       = (const float*)d_in[5];
  const float* bt       = (const float*)d_in[6];
  const float* Wq       = (const float*)d_in[7];
  const float* Wkv      = (const float*)d_in[8];
  const float* Wo       = (const float*)d_in[9];
  const float* Wb       = (const float*)d_in[10];
  const float* bb       = (const float*)d_in[11];
  float* out = (float*)d_out;

  cudaFuncSetAttribute(qkv_gemm_kernel,
                       cudaFuncAttributeMaxDynamicSharedMemorySize, GEMM_SMEM);
  cudaFuncSetAttribute(out_gemm_kernel,
                       cudaFuncAttributeMaxDynamicSharedMemorySize, GEMM_SMEM);
  cudaFuncSetAttribute(attn_fa2, cudaFuncAttributeMaxDynamicSharedMemorySize,
                       ATTN_SMEM);

  // Fork: bias (pure HBM, independent) runs concurrently with
  // prep -> ln -> qkv (tensor-bound). Join before attention, which reads
  // g_biasb. Event fork/join is the supported pattern under stream capture
  // and produces a branched graph. Objects are host-side (no device-mem
  // delta) and intentionally not destroyed while capture may reference them.
  cudaStream_t s1 = 0;
  cudaEvent_t evFork = 0, evJoin = 0;
  bool forked =
      (cudaStreamCreateWithFlags(&s1, cudaStreamNonBlocking) == cudaSuccess) &&
      (cudaEventCreateWithFlags(&evFork, cudaEventDisableTiming) == cudaSuccess) &&
      (cudaEventCreateWithFlags(&evJoin, cudaEventDisableTiming) == cudaSuccess);

  if (forked) {
    cudaEventRecord(evFork, 0);
    cudaStreamWaitEvent(s1, evFork, 0);
    bias_kernel<<<CB * CN * 2, 256, 0, s1>>>(ab, Wb, bb, seq_mask);
    cudaEventRecord(evJoin, s1);
  } else {
    bias_kernel<<<CB * CN * 2, 256>>>(ab, Wb, bb, seq_mask);
  }

  // main chain on the default stream
  prep_kernel<<<3584, 256>>>(x, Wq, Wkv, Wo, timep, Wt, bt);
  ln_film_kernel<<<CB * CN, 128>>>(x, gamma, seq_mask);
  qkv_gemm_kernel<<<384, 256, GEMM_SMEM>>>(seq_mask);

  if (forked) {
    cudaStreamWaitEvent(0, evJoin, 0);
  }

  attn_fa2<<<dim3(16, 32), 128, ATTN_SMEM>>>();
  out_gemm_kernel<<<128, 256, GEMM_SMEM>>>(out, seq_mask);
}